// round 2
// baseline (speedup 1.0000x reference)
#include <cuda_runtime.h>
#include <math.h>

#define IMG_W 512
#define IMG_H 512

// JPEG quantization tables (FACTOR = 1.0)
__constant__ float c_ytab[64] = {
    16, 11, 10, 16, 24, 40, 51, 61,
    12, 12, 14, 19, 26, 58, 60, 55,
    14, 13, 16, 24, 40, 57, 69, 56,
    14, 17, 22, 29, 51, 87, 80, 62,
    18, 22, 37, 56, 68,109,103, 77,
    24, 35, 55, 64, 81,104,113, 92,
    49, 64, 78, 87,103,121,120,101,
    72, 92, 95, 98,112,100,103, 99};

__constant__ float c_ctab[64] = {
    17, 18, 24, 47, 99, 99, 99, 99,
    18, 21, 26, 66, 99, 99, 99, 99,
    24, 26, 56, 99, 99, 99, 99, 99,
    47, 66, 99, 99, 99, 99, 99, 99,
    99, 99, 99, 99, 99, 99, 99, 99,
    99, 99, 99, 99, 99, 99, 99, 99,
    99, 99, 99, 99, 99, 99, 99, 99,
    99, 99, 99, 99, 99, 99, 99, 99};

// One CTA handles a 64(W) x 16(H) pixel tile of one image.
//   -> 16 Y 8x8 blocks (2 rows x 8 cols)
//   ->  4 Cb + 4 Cr 8x8 blocks (pooled 32x8 region)
__global__ void __launch_bounds__(256)
jpeg_compress_kernel(const float* __restrict__ img, float* __restrict__ out)
{
    __shared__ float sY [16][65];
    __shared__ float sCb[16][65];
    __shared__ float sCr[16][65];
    __shared__ float sCbP[8][33];
    __shared__ float sCrP[8][33];
    __shared__ float t1s[24][8][9];   // per-block DCT pass-1 scratch
    __shared__ float sC[64];          // C[x][u] = cos((2x+1)u pi/16)
    __shared__ float sScale[64];      // 0.25 * a(u) * a(v)

    const int t       = threadIdx.x;
    const int tileCol = blockIdx.x;   // 0..7   (64-px columns)
    const int tileRow = blockIdx.y;   // 0..31  (16-px rows)
    const int b       = blockIdx.z;   // batch
    const int nbatch  = gridDim.z;

    // --- DCT constants (double precision, once per CTA, 64 threads) ---
    if (t < 64) {
        int xx = t >> 3, uu = t & 7;
        sC[t] = (float)cos((2.0 * xx + 1.0) * uu * M_PI / 16.0);
        double au = uu ? 1.0 : 0.70710678118654752440;
        double ax = xx ? 1.0 : 0.70710678118654752440;
        sScale[t] = (float)(0.25 * ax * au);
    }

    // --- Phase 1: coalesced float4 loads, RGB -> YCbCr into smem ---
    const size_t plane = (size_t)IMG_H * IMG_W;
    const float* base = img + (size_t)b * 3 * plane
                      + (size_t)(tileRow * 16) * IMG_W + tileCol * 64;
    {
        int r  = t >> 4;           // 0..15 row within tile
        int c4 = (t & 15) * 4;     // column (multiple of 4)
        const float4 R4 = *reinterpret_cast<const float4*>(base + (size_t)r * IMG_W + c4);
        const float4 G4 = *reinterpret_cast<const float4*>(base + plane + (size_t)r * IMG_W + c4);
        const float4 B4 = *reinterpret_cast<const float4*>(base + 2 * plane + (size_t)r * IMG_W + c4);
        float Rv[4] = {R4.x, R4.y, R4.z, R4.w};
        float Gv[4] = {G4.x, G4.y, G4.z, G4.w};
        float Bv[4] = {B4.x, B4.y, B4.z, B4.w};
        #pragma unroll
        for (int i = 0; i < 4; i++) {
            float R = Rv[i] * 255.0f;
            float G = Gv[i] * 255.0f;
            float B = Bv[i] * 255.0f;
            sY [r][c4 + i] =  0.299f    * R + 0.587f    * G + 0.114f    * B;
            sCb[r][c4 + i] = -0.168736f * R - 0.331264f * G + 0.5f      * B + 128.0f;
            sCr[r][c4 + i] =  0.5f      * R - 0.418688f * G - 0.081312f * B + 128.0f;
        }
    }
    __syncthreads();

    // --- Phase 2: 2x2 average pool of Cb/Cr (16x64 -> 8x32) ---
    {
        int pr = t >> 5;           // 0..7
        int pc = t & 31;           // 0..31
        sCbP[pr][pc] = 0.25f * (sCb[2*pr][2*pc] + sCb[2*pr][2*pc+1] +
                                sCb[2*pr+1][2*pc] + sCb[2*pr+1][2*pc+1]);
        sCrP[pr][pc] = 0.25f * (sCr[2*pr][2*pc] + sCr[2*pr][2*pc+1] +
                                sCr[2*pr+1][2*pc] + sCr[2*pr+1][2*pc+1]);
    }
    __syncthreads();

    // --- Phase 3: 24 blocks x 8 threads: separable 8x8 DCT + quantize ---
    const int blk = t >> 3;   // 0..31 (24 active)
    const int x   = t & 7;    // row index (pass A) / output freq u (pass B)

    if (blk < 24) {
        // Pass A: t1[x][v] = sum_y (src[x][y] - 128) * C[y][v]
        float rowv[8];
        if (blk < 16) {
            int by = blk >> 3, bx = blk & 7;
            #pragma unroll
            for (int yy = 0; yy < 8; yy++)
                rowv[yy] = sY[by * 8 + x][bx * 8 + yy] - 128.0f;
        } else if (blk < 20) {
            int bx = blk - 16;
            #pragma unroll
            for (int yy = 0; yy < 8; yy++)
                rowv[yy] = sCbP[x][bx * 8 + yy] - 128.0f;
        } else {
            int bx = blk - 20;
            #pragma unroll
            for (int yy = 0; yy < 8; yy++)
                rowv[yy] = sCrP[x][bx * 8 + yy] - 128.0f;
        }
        #pragma unroll
        for (int v = 0; v < 8; v++) {
            float s = 0.0f;
            #pragma unroll
            for (int yy = 0; yy < 8; yy++)
                s = fmaf(rowv[yy], sC[yy * 8 + v], s);
            t1s[blk][x][v] = s;
        }
        __syncwarp();

        // Pass B: out[u][v] = scale[u][v] * sum_x C[x][u] * t1[x][v]; u = this lane
        const int u = x;
        float ov[8];
        #pragma unroll
        for (int v = 0; v < 8; v++) {
            float s = 0.0f;
            #pragma unroll
            for (int xx = 0; xx < 8; xx++)
                s = fmaf(sC[xx * 8 + u], t1s[blk][xx][v], s);
            ov[v] = s * sScale[u * 8 + v];
        }

        // Quantize + round (half-to-even, matches jnp.round) and store
        const bool isY = (blk < 16);
        size_t off;
        if (isY) {
            int by = blk >> 3, bx = blk & 7;
            int n = (tileRow * 2 + by) * 64 + (tileCol * 8 + bx);
            off = (size_t)b * 4096 * 64 + (size_t)n * 64 + u * 8;
        } else {
            size_t cbBase = (size_t)nbatch * 4096 * 64;
            int bx, comp;
            if (blk < 20) { bx = blk - 16; comp = 0; }
            else          { bx = blk - 20; comp = 1; }
            int n = tileRow * 32 + tileCol * 4 + bx;
            off = cbBase + (size_t)comp * nbatch * 1024 * 64
                + (size_t)b * 1024 * 64 + (size_t)n * 64 + u * 8;
        }
        const float* qt = isY ? c_ytab : c_ctab;
        float q[8];
        #pragma unroll
        for (int v = 0; v < 8; v++)
            q[v] = rintf(ov[v] / qt[u * 8 + v]);

        float4* dst = reinterpret_cast<float4*>(out + off);
        dst[0] = make_float4(q[0], q[1], q[2], q[3]);
        dst[1] = make_float4(q[4], q[5], q[6], q[7]);
    }
}

extern "C" void kernel_launch(void* const* d_in, const int* in_sizes, int n_in,
                              void* d_out, int out_size)
{
    const float* img = (const float*)d_in[0];
    float* out = (float*)d_out;
    int nbatch = in_sizes[0] / (3 * IMG_H * IMG_W);
    dim3 grid(IMG_W / 64, IMG_H / 16, nbatch);
    jpeg_compress_kernel<<<grid, 256>>>(img, out);
}

// round 3
// speedup vs baseline: 1.3241x; 1.3241x over previous
#include <cuda_runtime.h>
#include <math.h>

#define IMG_W 512
#define IMG_H 512

// DCT cosine magnitudes cos(k*pi/16)
#define F0 1.0f
#define F1 0.980785280f
#define F2 0.923879533f
#define F3 0.831469612f
#define F4 0.707106781f
#define F5 0.555570233f
#define F6 0.382683432f
#define F7 0.195090322f

// One CTA handles a 64(W) x 16(H) pixel tile of one image.
//   -> 16 Y 8x8 blocks (2 rows x 8 cols)
//   ->  4 Cb + 4 Cr 8x8 blocks (pooled 32x8 region)
__global__ void __launch_bounds__(256)
jpeg_compress_kernel(const float* __restrict__ img, float* __restrict__ out)
{
    // C[x][u] = cos((2x+1)*u*pi/16) — compile-time literals -> FFMA immediates
    constexpr float CM[8][8] = {
        { F0,  F1,  F2,  F3,  F4,  F5,  F6,  F7},
        { F0,  F3,  F6, -F7, -F4, -F1, -F2, -F5},
        { F0,  F5, -F6, -F1, -F4,  F7,  F2,  F3},
        { F0,  F7, -F2, -F5,  F4,  F3, -F6, -F1},
        { F0, -F7, -F2,  F5,  F4, -F3, -F6,  F1},
        { F0, -F5, -F6,  F1, -F4, -F7,  F2, -F3},
        { F0, -F3,  F6,  F7, -F4,  F1, -F2,  F5},
        { F0, -F1,  F2, -F3,  F4, -F5,  F6, -F7},
    };

    __shared__ float sY  [16][68];   // Y - 128, padded for float4 conflict-free access
    __shared__ float sCbP[8][36];    // pooled Cb (centered)
    __shared__ float sCrP[8][36];    // pooled Cr (centered)
    __shared__ float sQ  [128];      // [0:64) = scale/ytab, [64:128) = scale/ctab

    const int t       = threadIdx.x;
    const int tileCol = blockIdx.x;   // 0..7
    const int tileRow = blockIdx.y;   // 0..31
    const int b       = blockIdx.z;
    const int nbatch  = gridDim.z;

    // --- quant coefficient tables (once per CTA, double precision) ---
    if (t < 64) {
        constexpr int YT[64] = {
            16,11,10,16,24,40,51,61, 12,12,14,19,26,58,60,55,
            14,13,16,24,40,57,69,56, 14,17,22,29,51,87,80,62,
            18,22,37,56,68,109,103,77, 24,35,55,64,81,104,113,92,
            49,64,78,87,103,121,120,101, 72,92,95,98,112,100,103,99};
        constexpr int CT[64] = {
            17,18,24,47,99,99,99,99, 18,21,26,66,99,99,99,99,
            24,26,56,99,99,99,99,99, 47,66,99,99,99,99,99,99,
            99,99,99,99,99,99,99,99, 99,99,99,99,99,99,99,99,
            99,99,99,99,99,99,99,99, 99,99,99,99,99,99,99,99};
        int uu = t >> 3, vv = t & 7;
        double au = uu ? 1.0 : 0.70710678118654752440;
        double av = vv ? 1.0 : 0.70710678118654752440;
        double sc = 0.25 * au * av;
        sQ[t]      = (float)(sc / (double)YT[t]);
        sQ[64 + t] = (float)(sc / (double)CT[t]);
    }

    // --- Phase 1: coalesced float4 loads, RGB -> YCbCr, register chroma pooling ---
    const size_t plane = (size_t)IMG_H * IMG_W;
    const float* base = img + (size_t)b * 3 * plane
                      + (size_t)(tileRow * 16) * IMG_W + tileCol * 64;
    {
        const int r  = t >> 4;          // 0..15
        const int c4 = (t & 15) * 4;
        const float4 R4 = *reinterpret_cast<const float4*>(base + (size_t)r * IMG_W + c4);
        const float4 G4 = *reinterpret_cast<const float4*>(base + plane + (size_t)r * IMG_W + c4);
        const float4 B4 = *reinterpret_cast<const float4*>(base + 2 * plane + (size_t)r * IMG_W + c4);
        float Rv[4] = {R4.x, R4.y, R4.z, R4.w};
        float Gv[4] = {G4.x, G4.y, G4.z, G4.w};
        float Bv[4] = {B4.x, B4.y, B4.z, B4.w};
        float y[4], cb[4], cr[4];
        #pragma unroll
        for (int i = 0; i < 4; i++) {
            float R = Rv[i] * 255.0f;
            float G = Gv[i] * 255.0f;
            float B = Bv[i] * 255.0f;
            // store centered values (the +128/-128 pair cancels for the DCT input)
            y [i] =  0.299f    * R + 0.587f    * G + 0.114f    * B - 128.0f;
            cb[i] = -0.168736f * R - 0.331264f * G + 0.5f      * B;
            cr[i] =  0.5f      * R - 0.418688f * G - 0.081312f * B;
        }
        *reinterpret_cast<float4*>(&sY[r][c4]) = make_float4(y[0], y[1], y[2], y[3]);

        // horizontal pool in registers, vertical pool via shfl with partner row (lane ^ 16)
        float hcb0 = cb[0] + cb[1], hcb1 = cb[2] + cb[3];
        float hcr0 = cr[0] + cr[1], hcr1 = cr[2] + cr[3];
        float pcb0 = hcb0 + __shfl_xor_sync(0xffffffffu, hcb0, 16);
        float pcb1 = hcb1 + __shfl_xor_sync(0xffffffffu, hcb1, 16);
        float pcr0 = hcr0 + __shfl_xor_sync(0xffffffffu, hcr0, 16);
        float pcr1 = hcr1 + __shfl_xor_sync(0xffffffffu, hcr1, 16);
        if (!(t & 16)) {                 // even row of the pair writes pooled result
            int pr = r >> 1;             // 0..7
            int pc = (t & 15) * 2;       // 0..30
            *reinterpret_cast<float2*>(&sCbP[pr][pc]) = make_float2(0.25f * pcb0, 0.25f * pcb1);
            *reinterpret_cast<float2*>(&sCrP[pr][pc]) = make_float2(0.25f * pcr0, 0.25f * pcr1);
        }
    }
    __syncthreads();

    // --- Phase 3: 24 blocks x 8 threads, register-only separable DCT ---
    const int blk = t >> 3;   // 0..31 (24 active; warps 6-7 fully idle here)
    const int x   = t & 7;

    if (blk < 24) {
        float rowv[8];
        if (blk < 16) {
            int by = blk >> 3, bx = blk & 7;
            float4 a = *reinterpret_cast<const float4*>(&sY[by * 8 + x][bx * 8]);
            float4 c = *reinterpret_cast<const float4*>(&sY[by * 8 + x][bx * 8 + 4]);
            rowv[0]=a.x; rowv[1]=a.y; rowv[2]=a.z; rowv[3]=a.w;
            rowv[4]=c.x; rowv[5]=c.y; rowv[6]=c.z; rowv[7]=c.w;
        } else {
            const float (*src)[36] = (blk < 20) ? sCbP : sCrP;
            int bx = (blk < 20) ? (blk - 16) : (blk - 20);
            float4 a = *reinterpret_cast<const float4*>(&src[x][bx * 8]);
            float4 c = *reinterpret_cast<const float4*>(&src[x][bx * 8 + 4]);
            rowv[0]=a.x; rowv[1]=a.y; rowv[2]=a.z; rowv[3]=a.w;
            rowv[4]=c.x; rowv[5]=c.y; rowv[6]=c.z; rowv[7]=c.w;
        }

        // Pass A: d[v] = sum_y rowv[y] * C[y][v]   (immediate-operand FMAs)
        float d[8];
        #pragma unroll
        for (int v = 0; v < 8; v++) {
            float s = rowv[0] * CM[0][v];
            #pragma unroll
            for (int yy = 1; yy < 8; yy++)
                s = fmaf(rowv[yy], CM[yy][v], s);
            d[v] = s;
        }

        // In-register 8x8 transpose across the 8-lane group: after this,
        // lane v holds t1[x][v] in d[x].
        #pragma unroll
        for (int m = 1; m < 8; m <<= 1) {
            #pragma unroll
            for (int j0 = 0; j0 < 8; j0++) {
                if (j0 & m) continue;
                int j1 = j0 | m;
                float a   = (x & m) ? d[j0] : d[j1];
                float bsh = __shfl_xor_sync(0xffffffffu, a, m);
                if (x & m) d[j0] = bsh; else d[j1] = bsh;
            }
        }

        // Output offset for this block; this lane owns output column v = x
        const int v = x;
        size_t off;
        int qbase;
        if (blk < 16) {
            int by = blk >> 3, bx = blk & 7;
            int n = (tileRow * 2 + by) * 64 + (tileCol * 8 + bx);
            off = (size_t)b * 4096 * 64 + (size_t)n * 64;
            qbase = 0;
        } else {
            size_t cbBase = (size_t)nbatch * 4096 * 64;
            int bx, comp;
            if (blk < 20) { bx = blk - 16; comp = 0; }
            else          { bx = blk - 20; comp = 1; }
            int n = tileRow * 32 + tileCol * 4 + bx;
            off = cbBase + (size_t)comp * nbatch * 1024 * 64
                + (size_t)b * 1024 * 64 + (size_t)n * 64;
            qbase = 64;
        }

        // Pass B + fused quantize: out[u][v] = rint( (sum_x C[x][u]*d[x]) * scale/q )
        float* dst = out + off + v;
        #pragma unroll
        for (int u = 0; u < 8; u++) {
            float s = d[0] * CM[0][u];
            #pragma unroll
            for (int xx = 1; xx < 8; xx++)
                s = fmaf(d[xx], CM[xx][u], s);
            dst[u * 8] = rintf(s * sQ[qbase + u * 8 + v]);
        }
    }
}

extern "C" void kernel_launch(void* const* d_in, const int* in_sizes, int n_in,
                              void* d_out, int out_size)
{
    const float* img = (const float*)d_in[0];
    float* out = (float*)d_out;
    int nbatch = in_sizes[0] / (3 * IMG_H * IMG_W);
    dim3 grid(IMG_W / 64, IMG_H / 16, nbatch);
    jpeg_compress_kernel<<<grid, 256>>>(img, out);
}